// round 16
// baseline (speedup 1.0000x reference)
#include <cuda_runtime.h>

// ---------------- problem constants ----------------------------------------
#define CNUM   10000
#define KNUM   5
#define NNODES 50000
#define EMBD   200
#define FDIM   64
#define LNUM   3
#define HNUM   3
#define HID    256

#define EBLK   49        // chunks per head for edge/pool
#define CHUNK  205       // crystals per chunk
#define BATCH  16        // crystals per batch (warp <-> crystal)
#define NTHR   512

typedef unsigned long long ull;

__device__ __forceinline__ ull dup2(float x) {
    ull r; asm("mov.b64 %0, {%1, %1};" : "=l"(r) : "f"(x)); return r;
}
__device__ __forceinline__ void fma2(ull &d, ull a, ull b) {
    asm("fma.rn.f32x2 %0, %1, %2, %0;" : "+l"(d) : "l"(a), "l"(b));
}
__device__ __forceinline__ float2 unpack2(ull v) {
    float2 r; asm("mov.b64 {%0, %1}, %2;" : "=f"(r.x), "=f"(r.y) : "l"(v)); return r;
}
union F4U { float4 f; ull u[2]; float s[4]; };

// ---------------- static device scratch ------------------------------------
__device__ float g_X[(size_t)NNODES * FDIM];
__device__ float g_hout[HNUM][(size_t)NNODES * FDIM];
__device__ float g_pool[HNUM][(size_t)CNUM * FDIM];

// ---------------- smem layout (floats) — register-resident edge/pool -------
#define S_XS   0            // 80 x 64   = 5120 (staging)
#define S_G    5120         // 80 x 256  = 20480 (edge G; pool GM uses row 0..15)
#define S_B1G  25600        // 256
#define S_W2G  25856        // 256
#define S_B1M  26112        // 256
#define S_GATE 26368        // 16 x 32
#define S_AW   26880        // 16 x 32
#define S_SAS  27392        // 96
#define S_WNS  27488        // 2 x 128
#define FE_SMEM ((27488 + 256 + 32) * 4)    // ~111 KB -> big L1D carveout

// ---------------- kernel 1: embedding (128 nodes / block, fma2-tiled) ------
#define EMB_NB    128
#define EMB_WSM   0
#define EMB_BS    12800
#define EMB_XS    12864
#define EMB_SMEM  ((12864 + 25600) * 4)
__global__ void __launch_bounds__(256, 1)
embed_kernel(const float* __restrict__ ef,
             const float* __restrict__ W,
             const float* __restrict__ b,
             const float* __restrict__ ew) {
    extern __shared__ float sm[];
    float* Wsm = sm + EMB_WSM;
    float* bs  = sm + EMB_BS;
    float* Xs  = sm + EMB_XS;
    const int tid = threadIdx.x;
    const int warp = tid >> 5, lane = tid & 31;
    const int n0 = blockIdx.x * EMB_NB;
    const int nn = min(EMB_NB, NNODES - n0);

    for (int e = tid; e < EMBD; e += 256) Wsm[e * 64 + 63] = 0.f;
    for (int idx = tid; idx < EMBD * 63; idx += 256)
        Wsm[(idx / 63) * 64 + (idx % 63)] = W[idx];
    if (tid < 63) bs[tid] = b[tid];
    if (tid == 63) bs[63] = 0.f;
    for (int idx = tid; idx < nn * EMBD; idx += 256)
        Xs[idx] = ef[(size_t)n0 * EMBD + idx];
    __syncthreads();

    const int nb = warp * 16;
    ull acc[16];
    {
        ull binit = *(const ull*)&bs[2 * lane];
        #pragma unroll
        for (int i = 0; i < 16; i++) acc[i] = binit;
    }
    for (int e4 = 0; e4 < EMBD; e4 += 4) {
        ull w0 = *(const ull*)&Wsm[(e4 + 0) * 64 + 2 * lane];
        ull w1 = *(const ull*)&Wsm[(e4 + 1) * 64 + 2 * lane];
        ull w2 = *(const ull*)&Wsm[(e4 + 2) * 64 + 2 * lane];
        ull w3 = *(const ull*)&Wsm[(e4 + 3) * 64 + 2 * lane];
        #pragma unroll
        for (int i = 0; i < 16; i++) {
            float4 xv = *(const float4*)&Xs[(nb + i) * EMBD + e4];
            fma2(acc[i], dup2(xv.x), w0);
            fma2(acc[i], dup2(xv.y), w1);
            fma2(acc[i], dup2(xv.z), w2);
            fma2(acc[i], dup2(xv.w), w3);
        }
    }
    #pragma unroll
    for (int i = 0; i < 16; i++) {
        int n = nb + i;
        if (n < nn) {
            float2 o = unpack2(acc[i]);
            if (lane == 31) o.y = ew[n0 + n];
            *(float2*)&g_X[(size_t)(n0 + n) * FDIM + 2 * lane] = o;
        }
    }
}

// ---- dual register gemm: rows 5w..5w+4 of X @ (WA | WB) -> regs ------------
// warp owns its crystal's 5 rows x 256 cols; lane owns cols 8l..8l+7.
__device__ __forceinline__ void dual_gemm_regs(const float* __restrict__ xr,
                                               const float* __restrict__ WA,
                                               const float* __restrict__ WB,
                                               ull Aa[5][4], ull Bb[5][4],
                                               int lane) {
    #pragma unroll
    for (int i = 0; i < 5; i++)
        #pragma unroll
        for (int t = 0; t < 4; t++) { Aa[i][t] = 0ull; Bb[i][t] = 0ull; }
    const float* wa = WA + 8 * lane;
    const float* wb = WB + 8 * lane;
    for (int k2 = 0; k2 < 64; k2 += 2) {
        float2 a[5];
        #pragma unroll
        for (int i = 0; i < 5; i++)
            a[i] = *(const float2*)&xr[i * 64 + k2];
        #pragma unroll
        for (int kk = 0; kk < 2; kk++) {
            const int k = k2 + kk;
            F4U wa0, wa1, wb0, wb1;
            wa0.f = *(const float4*)&wa[k * 256];
            wa1.f = *(const float4*)&wa[k * 256 + 4];
            wb0.f = *(const float4*)&wb[k * 256];
            wb1.f = *(const float4*)&wb[k * 256 + 4];
            #pragma unroll
            for (int i = 0; i < 5; i++) {
                ull ad = dup2(kk == 0 ? a[i].x : a[i].y);
                fma2(Aa[i][0], ad, wa0.u[0]);
                fma2(Aa[i][1], ad, wa0.u[1]);
                fma2(Aa[i][2], ad, wa1.u[0]);
                fma2(Aa[i][3], ad, wa1.u[1]);
                fma2(Bb[i][0], ad, wb0.u[0]);
                fma2(Bb[i][1], ad, wb0.u[1]);
                fma2(Bb[i][2], ad, wb1.u[0]);
                fma2(Bb[i][3], ad, wb1.u[1]);
            }
        }
    }
}

// ---------------- kernel 2: fused proj + edge attention (register-res.) ----
__global__ void __launch_bounds__(NTHR, 1)
fused_edge(const float* __restrict__ gW1, const float* __restrict__ gb1,
           const float* __restrict__ gW2, const float* __restrict__ gb2,
           const float* __restrict__ mW1, const float* __restrict__ mb1,
           const float* __restrict__ mW2, const float* __restrict__ mb2,
           const float* __restrict__ gpow, const float* __restrict__ ew) {
    extern __shared__ float sm[];
    float* Xs    = sm + S_XS;
    float* G     = sm + S_G;
    float* b1g_s = sm + S_B1G;
    float* w2g_s = sm + S_W2G;
    float* b1m_s = sm + S_B1M;
    float* gateb = sm + S_GATE;
    float* awb   = sm + S_AW;
    float* sas   = sm + S_SAS;
    float* wns   = sm + S_WNS;

    const int tid  = threadIdx.x;
    const int warp = tid >> 5, lane = tid & 31;
    const int h     = blockIdx.x / EBLK;
    const int chunk = blockIdx.x % EBLK;
    const int cbeg = chunk * CHUNK;
    const int cend = min(cbeg + CHUNK, CNUM);

    const float* WgA = gW1 + (size_t)h * 128 * 256;
    const float* WgB = WgA + 64 * 256;
    const float* WmA = mW1 + (size_t)h * 128 * 256;
    const float* WmB = WmA + 64 * 256;
    const float* W2h = mW2 + (size_t)h * 256 * 64;

    if (tid < 256) {
        b1g_s[tid] = gb1[h * 256 + tid];
        w2g_s[tid] = gW2[h * 256 + tid];
        b1m_s[tid] = mb1[h * 256 + tid];
    }
    const float p    = gpow[h];
    const float b2gv = gb2[h];
    const float2 b2r = *(const float2*)&mb2[h * 64 + 2 * lane];
    float* hout = g_hout[h];

    // prologue: stage first batch (all threads)
    {
        const int nrow0 = (cend - cbeg < BATCH ? cend - cbeg : BATCH) * 5;
        for (int idx = tid; idx < 1280; idx += NTHR) {
            int r = idx >> 4;
            if (r < nrow0)
                *(float4*)&Xs[r * 64 + (idx & 15) * 4] =
                    *(const float4*)&g_X[(size_t)(cbeg * 5 + r) * 64 + (idx & 15) * 4];
        }
        if (tid < 128) {
            int w = tid >> 3, j = tid & 7;
            if (j < 5 && cbeg + w < cend)
                wns[tid] = powf(ew[(cbeg + w) * 5 + j], p);
        }
    }

    for (int cb = cbeg; cb < cend; cb += BATCH) {
        __syncthreads();   // staging visible to gemms
        const bool valid = (cb + warp < cend);
        const float* xr = &Xs[warp * 5 * 64];

        ull Aa[5][4], Bb[5][4];
        if (valid) {
            // gate dual gemm -> registers
            dual_gemm_regs(xr, WgA, WgB, Aa, Bb, lane);

            // gate (register-resident) + softmax
            float b1g_r[8], w2g_r[8];
            #pragma unroll
            for (int t = 0; t < 8; t++) {
                b1g_r[t] = b1g_s[8 * lane + t];
                w2g_r[t] = w2g_s[8 * lane + t];
            }
            #pragma unroll
            for (int i = 0; i < 5; i++) {
                float af[8];
                #pragma unroll
                for (int t = 0; t < 4; t++) {
                    float2 v = unpack2(Aa[i][t]);
                    af[2 * t]     = v.x + b1g_r[2 * t];
                    af[2 * t + 1] = v.y + b1g_r[2 * t + 1];
                }
                #pragma unroll
                for (int j = 0; j < 5; j++) {
                    float s = 0.f;
                    #pragma unroll
                    for (int t = 0; t < 4; t++) {
                        float2 bv = unpack2(Bb[j][t]);
                        float hv;
                        hv = af[2 * t]     + bv.x; hv = hv >= 0.f ? hv : 0.01f * hv; s += hv * w2g_r[2 * t];
                        hv = af[2 * t + 1] + bv.y; hv = hv >= 0.f ? hv : 0.01f * hv; s += hv * w2g_r[2 * t + 1];
                    }
                    #pragma unroll
                    for (int o = 16; o; o >>= 1) s += __shfl_xor_sync(0xffffffffu, s, o);
                    if (lane == 0) gateb[warp * 32 + i * 5 + j] = s + b2gv;
                }
            }
            __syncwarp();
            if (lane < 5) {
                int i = lane;
                float mx = -1e30f;
                #pragma unroll
                for (int j = 0; j < 5; j++) mx = fmaxf(mx, gateb[warp * 32 + i * 5 + j]);
                float v[5], s = 0.f;
                #pragma unroll
                for (int j = 0; j < 5; j++) {
                    v[j] = wns[warp * 8 + j] * expf(gateb[warp * 32 + i * 5 + j] - mx);
                    s += v[j];
                }
                float inv = 1.f / (s + 1e-10f);
                float sa = 0.f;
                #pragma unroll
                for (int j = 0; j < 5; j++) { float a = v[j] * inv; awb[warp * 32 + i * 5 + j] = a; sa += a; }
                sas[warp * 5 + i] = sa;
            }
            __syncwarp();

            // msg dual gemm (reuse registers)
            dual_gemm_regs(xr, WmA, WmB, Aa, Bb, lane);
        }
        __syncthreads();   // all Xs reads done: staging target is free

        // staging prefetch (all threads) — overlaps with G-build below
        {
            const int cb2 = cb + BATCH;
            if (cb2 < cend) {
                const int nrow2 = (cend - cb2 < BATCH ? cend - cb2 : BATCH) * 5;
                for (int idx = tid; idx < 1280; idx += NTHR) {
                    int r = idx >> 4;
                    if (r < nrow2)
                        *(float4*)&Xs[r * 64 + (idx & 15) * 4] =
                            *(const float4*)&g_X[(size_t)(cb2 * 5 + r) * 64 + (idx & 15) * 4];
                }
                if (tid < 128) {
                    int w = tid >> 3, j = tid & 7;
                    if (j < 5 && cb2 + w < cend)
                        wns[tid] = powf(ew[(cb2 + w) * 5 + j], p);
                }
            }
        }

        // G build (register-resident) -> smem G rows (own warp)
        if (valid) {
            float b1m_r[8];
            #pragma unroll
            for (int t = 0; t < 8; t++) b1m_r[t] = b1m_s[8 * lane + t];
            #pragma unroll
            for (int i = 0; i < 5; i++) {
                float mf[8];
                #pragma unroll
                for (int t = 0; t < 4; t++) {
                    float2 v = unpack2(Aa[i][t]);
                    mf[2 * t]     = v.x + b1m_r[2 * t];
                    mf[2 * t + 1] = v.y + b1m_r[2 * t + 1];
                }
                float gv[8];
                #pragma unroll
                for (int t = 0; t < 8; t++) gv[t] = 0.f;
                #pragma unroll
                for (int j = 0; j < 5; j++) {
                    float a = awb[warp * 32 + i * 5 + j];
                    #pragma unroll
                    for (int t = 0; t < 4; t++) {
                        float2 nv = unpack2(Bb[j][t]);
                        float hv;
                        hv = mf[2 * t]     + nv.x; hv = hv >= 0.f ? hv : 0.01f * hv; gv[2 * t]     += a * hv;
                        hv = mf[2 * t + 1] + nv.y; hv = hv >= 0.f ? hv : 0.01f * hv; gv[2 * t + 1] += a * hv;
                    }
                }
                *(float4*)&G[(warp * 5 + i) * 256 + 8 * lane]     = make_float4(gv[0], gv[1], gv[2], gv[3]);
                *(float4*)&G[(warp * 5 + i) * 256 + 8 * lane + 4] = make_float4(gv[4], gv[5], gv[6], gv[7]);
            }
        }
        __syncwarp();      // G rows are same-warp

        // final GEMM: warp owns its crystal's 5 G rows
        if (valid) {
            ull acc[5];
            #pragma unroll
            for (int i = 0; i < 5; i++) acc[i] = 0ull;
            #pragma unroll 2
            for (int k4 = 0; k4 < 256; k4 += 4) {
                ull w[4];
                #pragma unroll
                for (int kk = 0; kk < 4; kk++)
                    w[kk] = *(const ull*)&W2h[(k4 + kk) * 64 + 2 * lane];
                #pragma unroll
                for (int i = 0; i < 5; i++) {
                    F4U g; g.f = *(const float4*)&G[(5 * warp + i) * 256 + k4];
                    fma2(acc[i], dup2(g.s[0]), w[0]);
                    fma2(acc[i], dup2(g.s[1]), w[1]);
                    fma2(acc[i], dup2(g.s[2]), w[2]);
                    fma2(acc[i], dup2(g.s[3]), w[3]);
                }
            }
            #pragma unroll
            for (int i = 0; i < 5; i++) {
                int r = 5 * warp + i;
                float2 av = unpack2(acc[i]);
                float sa = sas[r];
                float2 o = make_float2(av.x + sa * b2r.x, av.y + sa * b2r.y);
                *(float2*)&hout[(size_t)(cb * 5 + r) * 64 + 2 * lane] = o;
            }
        }
        // loop-top __syncthreads covers staging visibility + wns
    }
}

// ---------------- kernel 3: residual combine over heads --------------------
__global__ void combine_layer() {
    size_t i = (size_t)blockIdx.x * 256 + threadIdx.x;
    if (i < (size_t)NNODES * FDIM)
        g_X[i] += (g_hout[0][i] + g_hout[1][i] + g_hout[2][i]) * (1.f / 3.f);
}

// ---------------- kernel 4: fused proj + pool (register-resident) ----------
__global__ void __launch_bounds__(NTHR, 1)
fused_pool(const float* __restrict__ gW1, const float* __restrict__ gb1,
           const float* __restrict__ gW2, const float* __restrict__ gb2,
           const float* __restrict__ mW1, const float* __restrict__ mb1,
           const float* __restrict__ mW2, const float* __restrict__ mb2,
           const float* __restrict__ cpow, const float* __restrict__ ew) {
    extern __shared__ float sm[];
    float* Xs    = sm + S_XS;
    float* GM    = sm + S_G;        // rows 0..15 of the G region
    float* b1g_s = sm + S_B1G;
    float* w2g_s = sm + S_W2G;
    float* b1m_s = sm + S_B1M;
    float* gateb = sm + S_GATE;
    float* awb   = sm + S_AW;
    float* sas   = sm + S_SAS;
    float* wns   = sm + S_WNS;      // 2 x 128 parity

    const int tid  = threadIdx.x;
    const int warp = tid >> 5, lane = tid & 31;
    const int h     = blockIdx.x / EBLK;
    const int chunk = blockIdx.x % EBLK;
    const int cbeg = chunk * CHUNK;
    const int cend = min(cbeg + CHUNK, CNUM);

    const float* W1g = gW1 + (size_t)h * 64 * 256;
    const float* W1m = mW1 + (size_t)h * 64 * 256;
    const float* W2h = mW2 + (size_t)h * 256 * 64;

    if (tid < 256) {
        b1g_s[tid] = gb1[h * 256 + tid];
        w2g_s[tid] = gW2[h * 256 + tid];
        b1m_s[tid] = mb1[h * 256 + tid];
    }
    const float p    = cpow[h];
    const float b2gv = gb2[h];
    const float2 b2r = *(const float2*)&mb2[h * 64 + 2 * lane];

    // prologue staging (parity 0)
    {
        const int nrow0 = (cend - cbeg < BATCH ? cend - cbeg : BATCH) * 5;
        for (int idx = tid; idx < 1280; idx += NTHR) {
            int r = idx >> 4;
            if (r < nrow0)
                *(float4*)&Xs[r * 64 + (idx & 15) * 4] =
                    *(const float4*)&g_X[(size_t)(cbeg * 5 + r) * 64 + (idx & 15) * 4];
        }
        if (tid < 128) {
            int w = tid >> 3, j = tid & 7;
            if (j < 5 && cbeg + w < cend)
                wns[tid] = powf(ew[(cbeg + w) * 5 + j], p);
        }
    }

    int par = 0;
    for (int cb = cbeg; cb < cend; cb += BATCH, par ^= 1) {
        __syncthreads();    // staging visible
        const bool valid = (cb + warp < cend);
        const float* xr = &Xs[warp * 5 * 64];

        ull Hg[5][4], Hm[5][4];
        if (valid)
            dual_gemm_regs(xr, W1g, W1m, Hg, Hm, lane);
        __syncthreads();    // Xs reads done

        // staging prefetch (all threads)
        {
            const int cb2 = cb + BATCH;
            if (cb2 < cend) {
                const int nrow2 = (cend - cb2 < BATCH ? cend - cb2 : BATCH) * 5;
                for (int idx = tid; idx < 1280; idx += NTHR) {
                    int r = idx >> 4;
                    if (r < nrow2)
                        *(float4*)&Xs[r * 64 + (idx & 15) * 4] =
                            *(const float4*)&g_X[(size_t)(cb2 * 5 + r) * 64 + (idx & 15) * 4];
                }
                if (tid < 128) {
                    int w = tid >> 3, j = tid & 7;
                    if (j < 5 && cb2 + w < cend)
                        wns[(par ^ 1) * 128 + tid] = powf(ew[(cb2 + w) * 5 + j], p);
                }
            }
        }

        if (valid) {
            float b1g_r[8], w2g_r[8], b1m_r[8];
            #pragma unroll
            for (int t = 0; t < 8; t++) {
                b1g_r[t] = b1g_s[8 * lane + t];
                w2g_r[t] = w2g_s[8 * lane + t];
                b1m_r[t] = b1m_s[8 * lane + t];
            }
            // gate per node (register-resident)
            #pragma unroll
            for (int i = 0; i < 5; i++) {
                float s = 0.f;
                #pragma unroll
                for (int t = 0; t < 4; t++) {
                    float2 v = unpack2(Hg[i][t]);
                    float hv;
                    hv = v.x + b1g_r[2 * t];     hv = hv >= 0.f ? hv : 0.01f * hv; s += hv * w2g_r[2 * t];
                    hv = v.y + b1g_r[2 * t + 1]; hv = hv >= 0.f ? hv : 0.01f * hv; s += hv * w2g_r[2 * t + 1];
                }
                #pragma unroll
                for (int o = 16; o; o >>= 1) s += __shfl_xor_sync(0xffffffffu, s, o);
                if (lane == 0) gateb[warp * 32 + i] = s + b2gv;
            }
            __syncwarp();
            if (lane == 0) {
                float mx = -1e30f;
                #pragma unroll
                for (int i = 0; i < 5; i++) mx = fmaxf(mx, gateb[warp * 32 + i]);
                float v[5], s = 0.f;
                #pragma unroll
                for (int i = 0; i < 5; i++) {
                    v[i] = wns[par * 128 + warp * 8 + i] * expf(gateb[warp * 32 + i] - mx);
                    s += v[i];
                }
                float inv = 1.f / (s + 1e-10f);
                float sa = 0.f;
                #pragma unroll
                for (int i = 0; i < 5; i++) { float a = v[i] * inv; awb[warp * 32 + i] = a; sa += a; }
                sas[warp] = sa;
            }
            __syncwarp();

            // weighted combine (register-resident) -> GM row warp
            float gv[8];
            #pragma unroll
            for (int t = 0; t < 8; t++) gv[t] = 0.f;
            #pragma unroll
            for (int i = 0; i < 5; i++) {
                float a = awb[warp * 32 + i];
                #pragma unroll
                for (int t = 0; t < 4; t++) {
                    float2 v = unpack2(Hm[i][t]);
                    float hv;
                    hv = v.x + b1m_r[2 * t];     hv = hv >= 0.f ? hv : 0.01f * hv; gv[2 * t]     += a * hv;
                    hv = v.y + b1m_r[2 * t + 1]; hv = hv >= 0.f ? hv : 0.01f * hv; gv[2 * t + 1] += a * hv;
                }
            }
            *(float4*)&GM[warp * 256 + 8 * lane]     = make_float4(gv[0], gv[1], gv[2], gv[3]);
            *(float4*)&GM[warp * 256 + 8 * lane + 4] = make_float4(gv[4], gv[5], gv[6], gv[7]);
        }
        __syncwarp();       // GM row is same-warp

        // final GEMM [16,256]@[256,64]: warp reads its own GM row
        if (valid) {
            ull acc = 0ull;
            #pragma unroll 2
            for (int k4 = 0; k4 < 256; k4 += 4) {
                ull w[4];
                #pragma unroll
                for (int kk = 0; kk < 4; kk++)
                    w[kk] = *(const ull*)&W2h[(k4 + kk) * 64 + 2 * lane];
                F4U g; g.f = *(const float4*)&GM[warp * 256 + k4];
                fma2(acc, dup2(g.s[0]), w[0]);
                fma2(acc, dup2(g.s[1]), w[1]);
                fma2(acc, dup2(g.s[2]), w[2]);
                fma2(acc, dup2(g.s[3]), w[3]);
            }
            float2 av = unpack2(acc);
            float sa = sas[warp];
            float2 o = make_float2(av.x + sa * b2r.x, av.y + sa * b2r.y);
            *(float2*)&g_pool[h][(size_t)(cb + warp) * 64 + 2 * lane] = o;
        }
        // loop-top __syncthreads covers
    }
}

// ---------------- kernel 5: final head mean ---------------------------------
__global__ void final_combine(float* __restrict__ out) {
    int i = blockIdx.x * 256 + threadIdx.x;
    if (i < CNUM * FDIM)
        out[i] = (g_pool[0][i] + g_pool[1][i] + g_pool[2][i]) * (1.f / 3.f);
}

// ---------------- host launcher ---------------------------------------------
extern "C" void kernel_launch(void* const* d_in, const int* in_sizes, int n_in,
                              void* d_out, int out_size) {
    int wi = 5;
    if (n_in > 5 && in_sizes[5] == 1) wi = 6;

    const float* elem_weights = (const float*)d_in[0];
    const float* elem_fea     = (const float*)d_in[1];
    const float* emb_W = (const float*)d_in[wi + 0];
    const float* emb_b = (const float*)d_in[wi + 1];
    const float* gW1   = (const float*)d_in[wi + 2];
    const float* gb1   = (const float*)d_in[wi + 3];
    const float* gW2   = (const float*)d_in[wi + 4];
    const float* gb2   = (const float*)d_in[wi + 5];
    const float* mW1   = (const float*)d_in[wi + 6];
    const float* mb1   = (const float*)d_in[wi + 7];
    const float* mW2   = (const float*)d_in[wi + 8];
    const float* mb2   = (const float*)d_in[wi + 9];
    const float* gpw   = (const float*)d_in[wi + 10];
    const float* cgW1  = (const float*)d_in[wi + 11];
    const float* cgb1  = (const float*)d_in[wi + 12];
    const float* cgW2  = (const float*)d_in[wi + 13];
    const float* cgb2  = (const float*)d_in[wi + 14];
    const float* cmW1  = (const float*)d_in[wi + 15];
    const float* cmb1  = (const float*)d_in[wi + 16];
    const float* cmW2  = (const float*)d_in[wi + 17];
    const float* cmb2  = (const float*)d_in[wi + 18];
    const float* cpw   = (const float*)d_in[wi + 19];

    cudaFuncSetAttribute(embed_kernel, cudaFuncAttributeMaxDynamicSharedMemorySize, EMB_SMEM);
    cudaFuncSetAttribute(fused_edge,   cudaFuncAttributeMaxDynamicSharedMemorySize, FE_SMEM);
    cudaFuncSetAttribute(fused_pool,   cudaFuncAttributeMaxDynamicSharedMemorySize, FE_SMEM);

    embed_kernel<<<(NNODES + EMB_NB - 1) / EMB_NB, 256, EMB_SMEM>>>(
        elem_fea, emb_W, emb_b, elem_weights);

    for (int l = 0; l < LNUM; l++) {
        fused_edge<<<HNUM * EBLK, NTHR, FE_SMEM>>>(
            gW1 + (size_t)l * HNUM * 128 * 256,
            gb1 + (size_t)l * HNUM * 256,
            gW2 + (size_t)l * HNUM * 256,
            gb2 + (size_t)l * HNUM,
            mW1 + (size_t)l * HNUM * 128 * 256,
            mb1 + (size_t)l * HNUM * 256,
            mW2 + (size_t)l * HNUM * 256 * 64,
            mb2 + (size_t)l * HNUM * 64,
            gpw + (size_t)l * HNUM,
            elem_weights);

        combine_layer<<<(NNODES * FDIM + 255) / 256, 256>>>();
    }

    fused_pool<<<HNUM * EBLK, NTHR, FE_SMEM>>>(cgW1, cgb1, cgW2, cgb2,
                                               cmW1, cmb1, cmW2, cmb2,
                                               cpw, elem_weights);

    final_combine<<<(CNUM * FDIM + 255) / 256, 256>>>((float*)d_out);
}

// round 17
// speedup vs baseline: 1.4128x; 1.4128x over previous
#include <cuda_runtime.h>

// ---------------- problem constants ----------------------------------------
#define CNUM   10000
#define KNUM   5
#define NNODES 50000
#define EMBD   200
#define FDIM   64
#define LNUM   3
#define HNUM   3
#define HID    256

#define EBLK   49        // chunks per head for edge/pool
#define CHUNK  205       // crystals per chunk
#define BATCH  16        // crystals per batch
#define NTHR   512

typedef unsigned long long ull;

__device__ __forceinline__ ull dup2(float x) {
    ull r; asm("mov.b64 %0, {%1, %1};" : "=l"(r) : "f"(x)); return r;
}
__device__ __forceinline__ void fma2(ull &d, ull a, ull b) {
    asm("fma.rn.f32x2 %0, %1, %2, %0;" : "+l"(d) : "l"(a), "l"(b));
}
__device__ __forceinline__ float2 unpack2(ull v) {
    float2 r; asm("mov.b64 {%0, %1}, %2;" : "=f"(r.x), "=f"(r.y) : "l"(v)); return r;
}
union F4U { float4 f; ull u[2]; float s[4]; };

// ---------------- static device scratch ------------------------------------
__device__ float g_X[(size_t)NNODES * FDIM];
__device__ float g_hout[HNUM][(size_t)NNODES * FDIM];
__device__ float g_pool[HNUM][(size_t)CNUM * FDIM];

// ---------------- smem layout (floats) — round-13/15 proven ----------------
#define S_XS   0            // 80 x 64
#define S_A    5120         // 80 x 256
#define S_B    25600        // 80 x 256
#define S_B1G  46080        // 256
#define S_W2G  46336        // 256
#define S_B1M  46592        // 256
#define S_GATE 46848        // 16 x 32
#define S_AW   47360        // 16 x 32
#define S_SAS  47872        // 96
#define S_WNS  47968        // 2 x 128 (parity-buffered; edge uses slot 0 only)
#define S_GM   48224        // 16 x 256 (pool combine target)
#define FE_SMEM ((48224 + 4096 + 32) * 4)

// ---------------- kernel 1: embedding (128 nodes / block, fma2-tiled) ------
#define EMB_NB    128
#define EMB_WSM   0
#define EMB_BS    12800
#define EMB_XS    12864
#define EMB_SMEM  ((12864 + 25600) * 4)
__global__ void __launch_bounds__(256, 1)
embed_kernel(const float* __restrict__ ef,
             const float* __restrict__ W,
             const float* __restrict__ b,
             const float* __restrict__ ew) {
    extern __shared__ float sm[];
    float* Wsm = sm + EMB_WSM;
    float* bs  = sm + EMB_BS;
    float* Xs  = sm + EMB_XS;
    const int tid = threadIdx.x;
    const int warp = tid >> 5, lane = tid & 31;
    const int n0 = blockIdx.x * EMB_NB;
    const int nn = min(EMB_NB, NNODES - n0);

    for (int e = tid; e < EMBD; e += 256) Wsm[e * 64 + 63] = 0.f;
    for (int idx = tid; idx < EMBD * 63; idx += 256)
        Wsm[(idx / 63) * 64 + (idx % 63)] = W[idx];
    if (tid < 63) bs[tid] = b[tid];
    if (tid == 63) bs[63] = 0.f;
    for (int idx = tid; idx < nn * EMBD; idx += 256)
        Xs[idx] = ef[(size_t)n0 * EMBD + idx];
    __syncthreads();

    const int nb = warp * 16;
    ull acc[16];
    {
        ull binit = *(const ull*)&bs[2 * lane];
        #pragma unroll
        for (int i = 0; i < 16; i++) acc[i] = binit;
    }
    for (int e4 = 0; e4 < EMBD; e4 += 4) {
        ull w0 = *(const ull*)&Wsm[(e4 + 0) * 64 + 2 * lane];
        ull w1 = *(const ull*)&Wsm[(e4 + 1) * 64 + 2 * lane];
        ull w2 = *(const ull*)&Wsm[(e4 + 2) * 64 + 2 * lane];
        ull w3 = *(const ull*)&Wsm[(e4 + 3) * 64 + 2 * lane];
        #pragma unroll
        for (int i = 0; i < 16; i++) {
            float4 xv = *(const float4*)&Xs[(nb + i) * EMBD + e4];
            fma2(acc[i], dup2(xv.x), w0);
            fma2(acc[i], dup2(xv.y), w1);
            fma2(acc[i], dup2(xv.z), w2);
            fma2(acc[i], dup2(xv.w), w3);
        }
    }
    #pragma unroll
    for (int i = 0; i < 16; i++) {
        int n = nb + i;
        if (n < nn) {
            float2 o = unpack2(acc[i]);
            if (lane == 31) o.y = ew[n0 + n];
            *(float2*)&g_X[(size_t)(n0 + n) * FDIM + 2 * lane] = o;
        }
    }
}

// ---- gemm80: [80,64] @ [64,256] -> smem; 16 warps: (col-half, row-group) ---
__device__ __noinline__ void gemm80(const float* __restrict__ Xs,
                                    const float* __restrict__ W,
                                    float* __restrict__ out,
                                    int lane, int wr, int wh) {
    const float* Wp = W + wh * 128 + 4 * lane;
    ull acc[10][2];
    #pragma unroll
    for (int i = 0; i < 10; i++) { acc[i][0] = 0ull; acc[i][1] = 0ull; }

    for (int k4 = 0; k4 < 64; k4 += 4) {
        float4 a[10];
        #pragma unroll
        for (int i = 0; i < 10; i++)
            a[i] = *(const float4*)&Xs[(wr + 8 * i) * 64 + k4];
        #pragma unroll
        for (int kk = 0; kk < 4; kk++) {
            F4U w; w.f = *(const float4*)&Wp[(k4 + kk) * 256];
            #pragma unroll
            for (int i = 0; i < 10; i++) {
                float av = kk == 0 ? a[i].x : kk == 1 ? a[i].y : kk == 2 ? a[i].z : a[i].w;
                ull ad = dup2(av);
                fma2(acc[i][0], ad, w.u[0]);
                fma2(acc[i][1], ad, w.u[1]);
            }
        }
    }
    #pragma unroll
    for (int i = 0; i < 10; i++) {
        F4U o;
        o.u[0] = acc[i][0]; o.u[1] = acc[i][1];
        *(float4*)&out[(wr + 8 * i) * 256 + wh * 128 + 4 * lane] = o.f;
    }
}

// ---------------- kernel 2: fused proj + edge attention --------------------
__global__ void __launch_bounds__(NTHR, 1)
fused_edge(const float* __restrict__ gW1, const float* __restrict__ gb1,
           const float* __restrict__ gW2, const float* __restrict__ gb2,
           const float* __restrict__ mW1, const float* __restrict__ mb1,
           const float* __restrict__ mW2, const float* __restrict__ mb2,
           const float* __restrict__ gpow, const float* __restrict__ ew) {
    extern __shared__ float sm[];
    float* Xs    = sm + S_XS;
    float* A     = sm + S_A;
    float* B     = sm + S_B;
    float* b1g_s = sm + S_B1G;
    float* w2g_s = sm + S_W2G;
    float* b1m_s = sm + S_B1M;
    float* gateb = sm + S_GATE;
    float* awb   = sm + S_AW;
    float* sas   = sm + S_SAS;
    float* wns   = sm + S_WNS;

    const int tid  = threadIdx.x;
    const int warp = tid >> 5, lane = tid & 31;
    const int wr = warp & 7, wh = warp >> 3;
    const int h     = blockIdx.x / EBLK;
    const int chunk = blockIdx.x % EBLK;
    const int cbeg = chunk * CHUNK;
    const int cend = min(cbeg + CHUNK, CNUM);

    const float* WgA = gW1 + (size_t)h * 128 * 256;
    const float* WgB = WgA + 64 * 256;
    const float* WmA = mW1 + (size_t)h * 128 * 256;
    const float* WmB = WmA + 64 * 256;
    const float* W2h = mW2 + (size_t)h * 256 * 64;

    if (tid < 256) {
        b1g_s[tid] = gb1[h * 256 + tid];
        w2g_s[tid] = gW2[h * 256 + tid];
        b1m_s[tid] = mb1[h * 256 + tid];
    }
    const float p    = gpow[h];
    const float b2gv = gb2[h];
    const float2 b2r = *(const float2*)&mb2[h * 64 + 2 * lane];
    float* hout = g_hout[h];

    // prologue: stage first batch (all threads)
    {
        const int nrow0 = (cend - cbeg < BATCH ? cend - cbeg : BATCH) * 5;
        for (int idx = tid; idx < 1280; idx += NTHR) {
            int r = idx >> 4;
            if (r < nrow0)
                *(float4*)&Xs[r * 64 + (idx & 15) * 4] =
                    *(const float4*)&g_X[(size_t)(cbeg * 5 + r) * 64 + (idx & 15) * 4];
        }
        if (tid < 128) {
            int w = tid >> 3, j = tid & 7;
            if (j < 5 && cbeg + w < cend)
                wns[tid] = powf(ew[(cbeg + w) * 5 + j], p);
        }
    }

    for (int cb = cbeg; cb < cend; cb += BATCH) {
        __syncthreads();   // staging visible + WAR on A,B from prev final gemm

        // gate projections
        gemm80(Xs, WgA, A, lane, wr, wh);
        gemm80(Xs, WgB, B, lane, wr, wh);
        __syncthreads();

        // gate + softmax: warp <-> crystal; float4 k=8*lane+t indexing
        {
            const int cc = warp;
            if (cb + cc < cend) {
                float w2g_r[8], b1g_r[8], b_r[5][8];
                *(float4*)&w2g_r[0] = *(const float4*)&w2g_s[8 * lane];
                *(float4*)&w2g_r[4] = *(const float4*)&w2g_s[8 * lane + 4];
                *(float4*)&b1g_r[0] = *(const float4*)&b1g_s[8 * lane];
                *(float4*)&b1g_r[4] = *(const float4*)&b1g_s[8 * lane + 4];
                #pragma unroll
                for (int j = 0; j < 5; j++) {
                    *(float4*)&b_r[j][0] = *(const float4*)&B[(cc * 5 + j) * 256 + 8 * lane];
                    *(float4*)&b_r[j][4] = *(const float4*)&B[(cc * 5 + j) * 256 + 8 * lane + 4];
                }
                #pragma unroll
                for (int i = 0; i < 5; i++) {
                    float gsr[8];
                    *(float4*)&gsr[0] = *(const float4*)&A[(cc * 5 + i) * 256 + 8 * lane];
                    *(float4*)&gsr[4] = *(const float4*)&A[(cc * 5 + i) * 256 + 8 * lane + 4];
                    #pragma unroll
                    for (int t = 0; t < 8; t++) gsr[t] += b1g_r[t];
                    #pragma unroll
                    for (int j = 0; j < 5; j++) {
                        float a = 0.f;
                        #pragma unroll
                        for (int t = 0; t < 8; t++) {
                            float hv = gsr[t] + b_r[j][t];
                            hv = hv >= 0.f ? hv : 0.01f * hv;
                            a += hv * w2g_r[t];
                        }
                        #pragma unroll
                        for (int o = 16; o; o >>= 1) a += __shfl_xor_sync(0xffffffffu, a, o);
                        if (lane == 0) gateb[cc * 32 + i * 5 + j] = a + b2gv;
                    }
                }
                __syncwarp();
                if (lane < 5) {
                    int i = lane;
                    float mx = -1e30f;
                    #pragma unroll
                    for (int j = 0; j < 5; j++) mx = fmaxf(mx, gateb[cc * 32 + i * 5 + j]);
                    float v[5], s = 0.f;
                    #pragma unroll
                    for (int j = 0; j < 5; j++) {
                        v[j] = wns[cc * 8 + j] * expf(gateb[cc * 32 + i * 5 + j] - mx);
                        s += v[j];
                    }
                    float inv = 1.f / (s + 1e-10f);
                    float sa = 0.f;
                    #pragma unroll
                    for (int j = 0; j < 5; j++) { float a = v[j] * inv; awb[cc * 32 + i * 5 + j] = a; sa += a; }
                    sas[cc * 5 + i] = sa;
                }
            }
        }
        __syncthreads();

        // msg projections (overwrite A,B)
        gemm80(Xs, WmA, A, lane, wr, wh);
        gemm80(Xs, WmB, B, lane, wr, wh);
        __syncthreads();   // Xs now dead for this batch

        // overlap phase: prefetch next batch's X/wns + G build (warp-local)
        {
            const int cb2 = cb + BATCH;
            if (cb2 < cend) {
                const int nrow2 = (cend - cb2 < BATCH ? cend - cb2 : BATCH) * 5;
                for (int idx = tid; idx < 1280; idx += NTHR) {
                    int r = idx >> 4;
                    if (r < nrow2)
                        *(float4*)&Xs[r * 64 + (idx & 15) * 4] =
                            *(const float4*)&g_X[(size_t)(cb2 * 5 + r) * 64 + (idx & 15) * 4];
                }
                if (tid < 128) {
                    int w = tid >> 3, j = tid & 7;
                    if (j < 5 && cb2 + w < cend)
                        wns[tid] = powf(ew[(cb2 + w) * 5 + j], p);
                }
            }

            // G build: float4 k=8*lane+t indexing; G stored at true k position
            const int cc = warp;
            if (cb + cc < cend) {
                float a_r[25], b1m_r[8];
                #pragma unroll
                for (int q = 0; q < 25; q++) a_r[q] = awb[cc * 32 + q];
                *(float4*)&b1m_r[0] = *(const float4*)&b1m_s[8 * lane];
                *(float4*)&b1m_r[4] = *(const float4*)&b1m_s[8 * lane + 4];
                float nb_r[5][8];
                #pragma unroll
                for (int j = 0; j < 5; j++) {
                    *(float4*)&nb_r[j][0] = *(const float4*)&B[(cc * 5 + j) * 256 + 8 * lane];
                    *(float4*)&nb_r[j][4] = *(const float4*)&B[(cc * 5 + j) * 256 + 8 * lane + 4];
                }
                #pragma unroll
                for (int i = 0; i < 5; i++) {
                    float mf[8];
                    *(float4*)&mf[0] = *(const float4*)&A[(cc * 5 + i) * 256 + 8 * lane];
                    *(float4*)&mf[4] = *(const float4*)&A[(cc * 5 + i) * 256 + 8 * lane + 4];
                    #pragma unroll
                    for (int t = 0; t < 8; t++) mf[t] += b1m_r[t];
                    float gv[8];
                    #pragma unroll
                    for (int t = 0; t < 8; t++) gv[t] = 0.f;
                    #pragma unroll
                    for (int j = 0; j < 5; j++) {
                        float a = a_r[i * 5 + j];
                        #pragma unroll
                        for (int t = 0; t < 8; t++) {
                            float hv = mf[t] + nb_r[j][t];
                            hv = hv >= 0.f ? hv : 0.01f * hv;
                            gv[t] += a * hv;
                        }
                    }
                    *(float4*)&A[(cc * 5 + i) * 256 + 8 * lane]     = *(float4*)&gv[0];
                    *(float4*)&A[(cc * 5 + i) * 256 + 8 * lane + 4] = *(float4*)&gv[4];
                }
            }
        }
        __syncwarp();      // G rows are same-warp: no CTA barrier needed

        // final GEMM: warp owns its crystal's 5 G rows (written by itself)
        {
            ull acc[5];
            #pragma unroll
            for (int i = 0; i < 5; i++) acc[i] = 0ull;
            #pragma unroll 2
            for (int k4 = 0; k4 < 256; k4 += 4) {
                ull w[4];
                #pragma unroll
                for (int kk = 0; kk < 4; kk++)
                    w[kk] = *(const ull*)&W2h[(k4 + kk) * 64 + 2 * lane];
                #pragma unroll
                for (int i = 0; i < 5; i++) {
                    F4U g; g.f = *(const float4*)&A[(5 * warp + i) * 256 + k4];
                    fma2(acc[i], dup2(g.s[0]), w[0]);
                    fma2(acc[i], dup2(g.s[1]), w[1]);
                    fma2(acc[i], dup2(g.s[2]), w[2]);
                    fma2(acc[i], dup2(g.s[3]), w[3]);
                }
            }
            if (cb + warp < cend) {
                #pragma unroll
                for (int i = 0; i < 5; i++) {
                    int r = 5 * warp + i;
                    float2 av = unpack2(acc[i]);
                    float sa = sas[r];
                    float2 o = make_float2(av.x + sa * b2r.x, av.y + sa * b2r.y);
                    *(float2*)&hout[(size_t)(cb * 5 + r) * 64 + 2 * lane] = o;
                }
            }
        }
        // no barrier: loop-top __syncthreads covers WAR on A,B and staging
    }
}

// ---------------- kernel 3: residual combine over heads --------------------
__global__ void combine_layer() {
    size_t i = (size_t)blockIdx.x * 256 + threadIdx.x;
    if (i < (size_t)NNODES * FDIM)
        g_X[i] += (g_hout[0][i] + g_hout[1][i] + g_hout[2][i]) * (1.f / 3.f);
}

// ---------------- kernel 4: fused proj + pool ------------------------------
__global__ void __launch_bounds__(NTHR, 1)
fused_pool(const float* __restrict__ gW1, const float* __restrict__ gb1,
           const float* __restrict__ gW2, const float* __restrict__ gb2,
           const float* __restrict__ mW1, const float* __restrict__ mb1,
           const float* __restrict__ mW2, const float* __restrict__ mb2,
           const float* __restrict__ cpow, const float* __restrict__ ew) {
    extern __shared__ float sm[];
    float* Xs    = sm + S_XS;
    float* A     = sm + S_A;
    float* B     = sm + S_B;
    float* b1g_s = sm + S_B1G;
    float* w2g_s = sm + S_W2G;
    float* b1m_s = sm + S_B1M;
    float* gateb = sm + S_GATE;
    float* awb   = sm + S_AW;
    float* sas   = sm + S_SAS;
    float* wns   = sm + S_WNS;   // 2 x 128: read slot par, prefetch writes par^1
    float* GM    = sm + S_GM;

    const int tid  = threadIdx.x;
    const int warp = tid >> 5, lane = tid & 31;
    const int wr = warp & 7, wh = warp >> 3;
    const int h     = blockIdx.x / EBLK;
    const int chunk = blockIdx.x % EBLK;
    const int cbeg = chunk * CHUNK;
    const int cend = min(cbeg + CHUNK, CNUM);

    const float* W1g = gW1 + (size_t)h * 64 * 256;
    const float* W1m = mW1 + (size_t)h * 64 * 256;
    const float* W2h = mW2 + (size_t)h * 256 * 64;

    if (tid < 256) {
        b1g_s[tid] = gb1[h * 256 + tid];
        w2g_s[tid] = gW2[h * 256 + tid];
        b1m_s[tid] = mb1[h * 256 + tid];
    }
    const float p    = cpow[h];
    const float b2gv = gb2[h];
    const float2 b2r = *(const float2*)&mb2[h * 64 + 2 * lane];

    // prologue staging (parity 0)
    {
        const int nrow0 = (cend - cbeg < BATCH ? cend - cbeg : BATCH) * 5;
        for (int idx = tid; idx < 1280; idx += NTHR) {
            int r = idx >> 4;
            if (r < nrow0)
                *(float4*)&Xs[r * 64 + (idx & 15) * 4] =
                    *(const float4*)&g_X[(size_t)(cbeg * 5 + r) * 64 + (idx & 15) * 4];
        }
        if (tid < 128) {
            int w = tid >> 3, j = tid & 7;
            if (j < 5 && cbeg + w < cend)
                wns[tid] = powf(ew[(cbeg + w) * 5 + j], p);
        }
    }

    int par = 0;
    for (int cb = cbeg; cb < cend; cb += BATCH, par ^= 1) {
        __syncthreads();    // staging visible + WAR on A,B

        gemm80(Xs, W1g, A, lane, wr, wh);   // gate hidden
        gemm80(Xs, W1m, B, lane, wr, wh);   // msg hidden
        __syncthreads();    // Xs dead; A,B complete

        // gate + softmax + combine (warp-local, reads wns[par]) + prefetch
        {
            const int cb2 = cb + BATCH;
            if (cb2 < cend) {
                const int nrow2 = (cend - cb2 < BATCH ? cend - cb2 : BATCH) * 5;
                for (int idx = tid; idx < 1280; idx += NTHR) {
                    int r = idx >> 4;
                    if (r < nrow2)
                        *(float4*)&Xs[r * 64 + (idx & 15) * 4] =
                            *(const float4*)&g_X[(size_t)(cb2 * 5 + r) * 64 + (idx & 15) * 4];
                }
                if (tid < 128) {
                    int w = tid >> 3, j = tid & 7;
                    if (j < 5 && cb2 + w < cend)
                        wns[(par ^ 1) * 128 + tid] = powf(ew[(cb2 + w) * 5 + j], p);
                }
            }

            const int cc = warp;
            if (cb + cc < cend) {
                float w2g_r[8], b1g_r[8], b1m_r[8];
                *(float4*)&w2g_r[0] = *(const float4*)&w2g_s[8 * lane];
                *(float4*)&w2g_r[4] = *(const float4*)&w2g_s[8 * lane + 4];
                *(float4*)&b1g_r[0] = *(const float4*)&b1g_s[8 * lane];
                *(float4*)&b1g_r[4] = *(const float4*)&b1g_s[8 * lane + 4];
                *(float4*)&b1m_r[0] = *(const float4*)&b1m_s[8 * lane];
                *(float4*)&b1m_r[4] = *(const float4*)&b1m_s[8 * lane + 4];
                #pragma unroll
                for (int i = 0; i < 5; i++) {
                    float af[8];
                    *(float4*)&af[0] = *(const float4*)&A[(cc * 5 + i) * 256 + 8 * lane];
                    *(float4*)&af[4] = *(const float4*)&A[(cc * 5 + i) * 256 + 8 * lane + 4];
                    float a = 0.f;
                    #pragma unroll
                    for (int t = 0; t < 8; t++) {
                        float hv = af[t] + b1g_r[t];
                        hv = hv >= 0.f ? hv : 0.01f * hv;
                        a += hv * w2g_r[t];
                    }
                    #pragma unroll
                    for (int o = 16; o; o >>= 1) a += __shfl_xor_sync(0xffffffffu, a, o);
                    if (lane == 0) gateb[cc * 32 + i] = a + b2gv;
                }
                __syncwarp();
                if (lane == 0) {
                    float mx = -1e30f;
                    #pragma unroll
                    for (int i = 0; i < 5; i++) mx = fmaxf(mx, gateb[cc * 32 + i]);
                    float v[5], s = 0.f;
                    #pragma unroll
                    for (int i = 0; i < 5; i++) {
                        v[i] = wns[par * 128 + cc * 8 + i] * expf(gateb[cc * 32 + i] - mx);
                        s += v[i];
                    }
                    float inv = 1.f / (s + 1e-10f);
                    float sa = 0.f;
                    #pragma unroll
                    for (int i = 0; i < 5; i++) { float a = v[i] * inv; awb[cc * 32 + i] = a; sa += a; }
                    sas[cc] = sa;
                }
                __syncwarp();

                float a0 = awb[cc * 32 + 0], a1 = awb[cc * 32 + 1], a2 = awb[cc * 32 + 2];
                float a3 = awb[cc * 32 + 3], a4 = awb[cc * 32 + 4];
                float gv[8];
                #pragma unroll
                for (int t = 0; t < 8; t++) gv[t] = 0.f;
                #pragma unroll
                for (int j = 0; j < 5; j++) {
                    float aj = j == 0 ? a0 : j == 1 ? a1 : j == 2 ? a2 : j == 3 ? a3 : a4;
                    float bf[8];
                    *(float4*)&bf[0] = *(const float4*)&B[(cc * 5 + j) * 256 + 8 * lane];
                    *(float4*)&bf[4] = *(const float4*)&B[(cc * 5 + j) * 256 + 8 * lane + 4];
                    #pragma unroll
                    for (int t = 0; t < 8; t++) {
                        float hv = bf[t] + b1m_r[t];
                        hv = hv >= 0.f ? hv : 0.01f * hv;
                        gv[t] += aj * hv;
                    }
                }
                *(float4*)&GM[cc * 256 + 8 * lane]     = *(float4*)&gv[0];
                *(float4*)&GM[cc * 256 + 8 * lane + 4] = *(float4*)&gv[4];
            }
        }
        __syncwarp();       // GM row is same-warp

        // final GEMM [16,256]@[256,64]: warp reads its own GM row
        {
            ull acc = 0ull;
            #pragma unroll 2
            for (int k4 = 0; k4 < 256; k4 += 4) {
                ull w[4];
                #pragma unroll
                for (int kk = 0; kk < 4; kk++)
                    w[kk] = *(const ull*)&W2h[(k4 + kk) * 64 + 2 * lane];
                F4U g; g.f = *(const float4*)&GM[warp * 256 + k4];
                fma2(acc, dup2(g.s[0]), w[0]);
                fma2(acc, dup2(g.s[1]), w[1]);
                fma2(acc, dup2(g.s[2]), w[2]);
                fma2(acc, dup2(g.s[3]), w[3]);
            }
            if (cb + warp < cend) {
                float2 av = unpack2(acc);
                float sa = sas[warp];
                float2 o = make_float2(av.x + sa * b2r.x, av.y + sa * b2r.y);
                *(float2*)&g_pool[h][(size_t)(cb + warp) * 64 + 2 * lane] = o;
            }
        }
        // no barrier: loop-top __syncthreads covers
    }
}

// ---------------- kernel 5: final head mean ---------------------------------
__global__ void final_combine(float* __restrict__ out) {
    int i = blockIdx.x * 256 + threadIdx.x;
    if (i < CNUM * FDIM)
        out[i] = (g_pool[0][i] + g_pool[1][i] + g_pool[2][i]) * (1.f / 3.f);
}

// ---------------- host launcher ---------------------------------------------
extern "C" void kernel_launch(void* const* d_in, const int* in_sizes, int n_in,
                              void* d_out, int out_size) {
    int wi = 5;
    if (n_in > 5 && in_sizes[5] == 1) wi = 6;

    const float* elem_weights = (const float*)d_in[0];
    const float* elem_fea     = (const float*)d_in[1];
    const float* emb_W = (const float*)d_in[wi + 0];
    const float* emb_b = (const float*)d_in[wi + 1];
    const float* gW1   = (const float*)d_in[wi + 2];
    const float* gb1   = (const float*)d_in[wi + 3];
    const float* gW2   = (const float*)d_in[wi + 4];
    const float* gb2   = (const float*)d_in[wi + 5];
    const float* mW1   = (const float*)d_in[wi + 6];
    const float* mb1   = (const float*)d_in[wi + 7];
    const float* mW2   = (const float*)d_in[wi + 8];
    const float* mb2   = (const float*)d_in[wi + 9];
    const float* gpw   = (const float*)d_in[wi + 10];
    const float* cgW1  = (const float*)d_in[wi + 11];
    const float* cgb1  = (const float*)d_in[wi + 12];
    const float* cgW2  = (const float*)d_in[wi + 13];
    const float* cgb2  = (const float*)d_in[wi + 14];
    const float* cmW1  = (const float*)d_in[wi + 15];
    const float* cmb1  = (const float*)d_in[wi + 16];
    const float* cmW2  = (const float*)d_in[wi + 17];
    const float* cmb2  = (const float*)d_in[wi + 18];
    const float* cpw   = (const float*)d_in[wi + 19];

    cudaFuncSetAttribute(embed_kernel, cudaFuncAttributeMaxDynamicSharedMemorySize, EMB_SMEM);
    cudaFuncSetAttribute(fused_edge,   cudaFuncAttributeMaxDynamicSharedMemorySize, FE_SMEM);
    cudaFuncSetAttribute(fused_pool,   cudaFuncAttributeMaxDynamicSharedMemorySize, FE_SMEM);

    embed_kernel<<<(NNODES + EMB_NB - 1) / EMB_NB, 256, EMB_SMEM>>>(
        elem_fea, emb_W, emb_b, elem_weights);

    for (int l = 0; l < LNUM; l++) {
        fused_edge<<<HNUM * EBLK, NTHR, FE_SMEM>>>(
            gW1 + (size_t)l * HNUM * 128 * 256,
            gb1 + (size_t)l * HNUM * 256,
            gW2 + (size_t)l * HNUM * 256,
            gb2 + (size_t)l * HNUM,
            mW1 + (size_t)l * HNUM * 128 * 256,
            mb1 + (size_t)l * HNUM * 256,
            mW2 + (size_t)l * HNUM * 256 * 64,
            mb2 + (size_t)l * HNUM * 64,
            gpw + (size_t)l * HNUM,
            elem_weights);

        combine_layer<<<(NNODES * FDIM + 255) / 256, 256>>>();
    }

    fused_pool<<<HNUM * EBLK, NTHR, FE_SMEM>>>(cgW1, cgb1, cgW2, cgb2,
                                               cmW1, cmb1, cmW2, cmb2,
                                               cpw, elem_weights);

    final_combine<<<(CNUM * FDIM + 255) / 256, 256>>>((float*)d_out);
}